// round 15
// baseline (speedup 1.0000x reference)
#include <cuda_runtime.h>
#include <cstdint>

typedef unsigned long long u64;

#define Bn   16
#define R    360
#define RPAD 384   // padded row length (float2 units) for u/v scratch
#define K1_CTAS 360
#define K2_CTAS 576

// Scratch: u2[b][dpair k][i] = (u[i][2k], u[i][2k+1]) packed fp32x2; same for v (v includes +b_out)
__device__ u64 g_u2[Bn * 32 * RPAD];
__device__ u64 g_v2[Bn * 32 * RPAD];
// Monotonic per-producer completion counters + consumer run counter (never reset; replay-safe)
__device__ u64 g_flag[K1_CTAS];
__device__ u64 g_cons;

// ---------- packed fp32x2 helpers (sm_100+) ----------
__device__ __forceinline__ u64 pack2(float x, float y) {
    u64 d; asm("mov.b64 %0, {%1, %2};" : "=l"(d) : "f"(x), "f"(y)); return d;
}
__device__ __forceinline__ void unpack2(u64 a, float &x, float &y) {
    asm("mov.b64 {%0, %1}, %2;" : "=f"(x), "=f"(y) : "l"(a));
}
__device__ __forceinline__ void ffma2(u64 &d, u64 a, u64 b) {
    asm("fma.rn.f32x2 %0, %1, %2, %0;" : "+l"(d) : "l"(a), "l"(b));
}
// acc += w * relu(u+v)  (R10-proven form)
__device__ __forceinline__ void relu_dot2(u64 &acc, u64 u, u64 v, u64 w) {
    u64 s;
    asm("add.rn.f32x2 %0, %1, %2;" : "=l"(s) : "l"(u), "l"(v));
    float lo, hi; unpack2(s, lo, hi);
    lo = fmaxf(lo, 0.0f); hi = fmaxf(hi, 0.0f);
    s = pack2(lo, hi);
    ffma2(acc, s, w);
}

// ============================================================================
// Kernel 1 (R10-proven body): u = x @ Wout[0:64], v = x @ Wout[64:128] + b_out
// 360 blocks x 16 rows. PDL-triggers EARLY; publishes per-CTA flag at the end.
// ============================================================================
__global__ __launch_bounds__(256, 3) void k1_uv(
    const float* __restrict__ x,      // [5760][64]
    const float* __restrict__ Wout,   // [128][64]
    const float* __restrict__ bout)   // [64]
{
#if __CUDA_ARCH__ >= 900
    cudaTriggerProgrammaticLaunchCompletion();   // let k2 launch & overlap NOW
#endif
    __shared__ u64 xs[16][33];
    __shared__ u64 Wu[32][64];
    __shared__ u64 Wv[32][64];

    const int t = threadIdx.x;
    const int row0 = blockIdx.x * 16;

    {
        const int c = t & 63, p0 = t >> 6;
        #pragma unroll
        for (int p = p0; p < 32; p += 4) {
            Wu[p][c] = pack2(Wout[(2 * p) * 64 + c],      Wout[(2 * p + 1) * 64 + c]);
            Wv[p][c] = pack2(Wout[(64 + 2 * p) * 64 + c], Wout[(65 + 2 * p) * 64 + c]);
        }
    }
    {
        const u64* x2 = (const u64*)x;
        #pragma unroll
        for (int idx = t; idx < 16 * 32; idx += 256) {
            const int r = idx >> 5, lane = idx & 31;
            xs[r][lane] = x2[(size_t)(row0 + r) * 32 + lane];
        }
    }
    __syncthreads();

    const int row  = t & 15;
    const int g    = t >> 4;
    const int ccol = (g & 7) * 8;
    const bool isv = (g >= 8);
    const u64 (*Ws)[64] = isv ? Wv : Wu;

    u64 acc[8];
    #pragma unroll
    for (int j = 0; j < 8; j++) acc[j] = 0ull;

    #pragma unroll
    for (int p = 0; p < 32; p++) {
        const u64 xv = xs[row][p];
        ulonglong2 wa = *(const ulonglong2*)&Ws[p][ccol];
        ulonglong2 wb = *(const ulonglong2*)&Ws[p][ccol + 2];
        ulonglong2 wc = *(const ulonglong2*)&Ws[p][ccol + 4];
        ulonglong2 wd = *(const ulonglong2*)&Ws[p][ccol + 6];
        ffma2(acc[0], xv, wa.x);  ffma2(acc[1], xv, wa.y);
        ffma2(acc[2], xv, wb.x);  ffma2(acc[3], xv, wb.y);
        ffma2(acc[4], xv, wc.x);  ffma2(acc[5], xv, wc.y);
        ffma2(acc[6], xv, wd.x);  ffma2(acc[7], xv, wd.y);
    }

    const int grow = row0 + row;
    const int bb = grow / 360;
    const int i = grow - bb * 360;
    u64* gdst = isv ? g_v2 : g_u2;
    #pragma unroll
    for (int j = 0; j < 8; j += 2) {
        float l0, h0, l1, h1;
        unpack2(acc[j],     l0, h0);
        unpack2(acc[j + 1], l1, h1);
        float v0 = l0 + h0, v1 = l1 + h1;
        const int dd = ccol + j;
        if (isv) { v0 += __ldg(&bout[dd]); v1 += __ldg(&bout[dd + 1]); }
        gdst[(bb * 32 + (dd >> 1)) * RPAD + i] = pack2(v0, v1);
    }

    // Publish: release this CTA's rows to consumers
    __threadfence();
    __syncthreads();
    if (t == 0) atomicAdd(&g_flag[blockIdx.x], 1ull);
}

// ============================================================================
// Kernel 2 (R10-proven body): waits only on the ~10 producer CTAs it needs.
// ============================================================================
__global__ __launch_bounds__(256, 4) void k2_pair(
    const float* __restrict__ Wcat,   // [64]
    const float* __restrict__ bcat,   // [1]
    float* __restrict__ out)          // [16*360*360]
{
    __shared__ u64 Us[32][64];    // [dpair][send]
    __shared__ u64 Vs[32][64];    // [dpair][rec]
    __shared__ u64 Ww[32];        // packed Wcat pairs

    const int t = threadIdx.x;
    const int b  = blockIdx.z;
    const int s0 = blockIdx.x * 64;
    const int r0 = blockIdx.y * 64;

    // Non-dependent prologue (overlaps k1 under PDL)
    if (t < 32) Ww[t] = ((const u64*)Wcat)[t];
    const float bc = __ldg(bcat);

    // Wait for exactly the producers covering our u-rows and v-rows
    if (t == 0) {
        u64 old = atomicAdd(&g_cons, 1ull);
        const u64 target = old / (u64)K2_CTAS + 1ull;   // this run's epoch
        const int base = b * 360;
        const int ranges[4] = { (base + s0) >> 4, (base + s0 + 63) >> 4,
                                (base + r0) >> 4, (base + r0 + 63) >> 4 };
        long long tstart = clock64();
        #pragma unroll
        for (int rr = 0; rr < 2; rr++) {
            for (int c = ranges[2 * rr]; c <= ranges[2 * rr + 1]; c++) {
                while (true) {
                    u64 cur;
                    asm volatile("ld.acquire.gpu.u64 %0, [%1];"
                                 : "=l"(cur) : "l"(&g_flag[c]) : "memory");
                    if (cur >= target) break;
                    if (clock64() - tstart > 200000000ll) break;  // escape hatch
                    __nanosleep(64);
                }
            }
        }
    }
    __syncthreads();

    {
        const int c = t & 63, k0 = t >> 6;
        const u64* gu = g_u2 + b * 32 * RPAD + s0 + c;
        const u64* gv = g_v2 + b * 32 * RPAD + r0 + c;
        #pragma unroll
        for (int k = k0; k < 32; k += 4) {
            Us[k][c] = gu[k * RPAD];
            Vs[k][c] = gv[k * RPAD];
        }
    }
    __syncthreads();

    const int lane = t & 31;       // sends 2*lane, 2*lane+1 (conflict-free LDS.128)
    const int wg   = t >> 5;       // recs 8*wg .. 8*wg+7 (broadcast LDS.128)

    u64 acc[8][2];
    #pragma unroll
    for (int i = 0; i < 8; i++) { acc[i][0] = 0ull; acc[i][1] = 0ull; }

    #pragma unroll 8
    for (int k = 0; k < 32; k++) {
        const u64 w2 = Ww[k];
        ulonglong2 ua = *(const ulonglong2*)&Us[k][2 * lane];
        u64 vv[8];
        #pragma unroll
        for (int q = 0; q < 4; q++) {
            ulonglong2 va = *(const ulonglong2*)&Vs[k][8 * wg + 2 * q];
            vv[2 * q] = va.x; vv[2 * q + 1] = va.y;
        }
        #pragma unroll
        for (int i = 0; i < 8; i++) {
            relu_dot2(acc[i][0], ua.x, vv[i], w2);
            relu_dot2(acc[i][1], ua.y, vv[i], w2);
        }
    }

    const int s = s0 + 2 * lane;
    if (s < R) {
        #pragma unroll
        for (int i = 0; i < 8; i++) {
            const int rec = r0 + 8 * wg + i;
            if (rec < R) {
                float l0, h0, l1, h1;
                unpack2(acc[i][0], l0, h0);
                unpack2(acc[i][1], l1, h1);
                float2 o;
                o.x = fmaxf(l0 + h0 + bc, 0.0f);
                o.y = fmaxf(l1 + h1 + bc, 0.0f);
                *(float2*)&out[((size_t)(b * R + rec)) * R + s] = o;
            }
        }
    }
}

extern "C" void kernel_launch(void* const* d_in, const int* in_sizes, int n_in,
                              void* d_out, int out_size) {
    (void)in_sizes; (void)n_in; (void)out_size;
    const float* x    = (const float*)d_in[0];  // (16,360,64)
    const float* Wout = (const float*)d_in[1];  // (128,64)
    const float* bout = (const float*)d_in[2];  // (64)
    const float* Wcat = (const float*)d_in[3];  // (64,1)
    const float* bcat = (const float*)d_in[4];  // (1)
    float* out = (float*)d_out;                 // (16,360,360,1) fp32

    k1_uv<<<K1_CTAS, 256>>>(x, Wout, bout);    // 5760 rows / 16

    // PDL launch: k1 triggers at its TOP, so k2 overlaps k1's execution;
    // per-tile flags provide the actual data dependency.
    cudaLaunchConfig_t cfg = {};
    cfg.gridDim  = dim3(6, 6, 16);
    cfg.blockDim = dim3(256, 1, 1);
    cfg.stream   = 0;
    cudaLaunchAttribute attrs[1];
    attrs[0].id = cudaLaunchAttributeProgrammaticStreamSerialization;
    attrs[0].val.programmaticStreamSerializationAllowed = 1;
    cfg.attrs = attrs;
    cfg.numAttrs = 1;
    cudaLaunchKernelEx(&cfg, k2_pair, Wcat, bcat, out);
}

// round 16
// speedup vs baseline: 3622.0670x; 3622.0670x over previous
#include <cuda_runtime.h>
#include <cstdint>

typedef unsigned long long u64;

#define Bn   16
#define R    360
#define RPAD 384   // padded row length (float2 units) for u/v scratch

// Scratch: u2[b][dpair k][i] = (u[i][2k], u[i][2k+1]) packed fp32x2; same for v (v includes +b_out)
// __device__ globals are zero-initialized; pad [360,384) stays zero (k1 never writes it).
__device__ u64 g_u2[Bn * 32 * RPAD];
__device__ u64 g_v2[Bn * 32 * RPAD];

// ---------- packed fp32x2 helpers (sm_100+) ----------
__device__ __forceinline__ u64 pack2(float x, float y) {
    u64 d; asm("mov.b64 %0, {%1, %2};" : "=l"(d) : "f"(x), "f"(y)); return d;
}
__device__ __forceinline__ void unpack2(u64 a, float &x, float &y) {
    asm("mov.b64 {%0, %1}, %2;" : "=f"(x), "=f"(y) : "l"(a));
}
__device__ __forceinline__ void ffma2(u64 &d, u64 a, u64 b) {
    asm("fma.rn.f32x2 %0, %1, %2, %0;" : "+l"(d) : "l"(a), "l"(b));
}
// acc += w * relu(u+v)  (proven form; ptxas colors {lo,hi} onto the pair)
__device__ __forceinline__ void relu_dot2(u64 &acc, u64 u, u64 v, u64 w) {
    u64 s;
    asm("add.rn.f32x2 %0, %1, %2;" : "=l"(s) : "l"(u), "l"(v));
    float lo, hi; unpack2(s, lo, hi);
    lo = fmaxf(lo, 0.0f); hi = fmaxf(hi, 0.0f);
    s = pack2(lo, hi);
    ffma2(acc, s, w);
}

// ============================================================================
// Kernel 1 (R10-proven): u = x @ Wout[0:64], v = x @ Wout[64:128] + b_out
// 360 blocks x 16 rows, 3 CTAs/SM -> single co-resident wave across the chip.
// ============================================================================
__global__ __launch_bounds__(256, 3) void k1_uv(
    const float* __restrict__ x,      // [5760][64]
    const float* __restrict__ Wout,   // [128][64]
    const float* __restrict__ bout)   // [64]
{
    __shared__ u64 xs[16][33];
    __shared__ u64 Wu[32][64];
    __shared__ u64 Wv[32][64];

    const int t = threadIdx.x;
    const int row0 = blockIdx.x * 16;

    {
        const int c = t & 63, p0 = t >> 6;
        #pragma unroll
        for (int p = p0; p < 32; p += 4) {
            Wu[p][c] = pack2(Wout[(2 * p) * 64 + c],      Wout[(2 * p + 1) * 64 + c]);
            Wv[p][c] = pack2(Wout[(64 + 2 * p) * 64 + c], Wout[(65 + 2 * p) * 64 + c]);
        }
    }
    {
        const u64* x2 = (const u64*)x;
        #pragma unroll
        for (int idx = t; idx < 16 * 32; idx += 256) {
            const int r = idx >> 5, lane = idx & 31;
            xs[r][lane] = x2[(size_t)(row0 + r) * 32 + lane];
        }
    }
    __syncthreads();

    const int row  = t & 15;
    const int g    = t >> 4;
    const int ccol = (g & 7) * 8;     // columns ccol..ccol+7
    const bool isv = (g >= 8);
    const u64 (*Ws)[64] = isv ? Wv : Wu;

    u64 acc[8];
    #pragma unroll
    for (int j = 0; j < 8; j++) acc[j] = 0ull;

    #pragma unroll
    for (int p = 0; p < 32; p++) {
        const u64 xv = xs[row][p];
        ulonglong2 wa = *(const ulonglong2*)&Ws[p][ccol];
        ulonglong2 wb = *(const ulonglong2*)&Ws[p][ccol + 2];
        ulonglong2 wc = *(const ulonglong2*)&Ws[p][ccol + 4];
        ulonglong2 wd = *(const ulonglong2*)&Ws[p][ccol + 6];
        ffma2(acc[0], xv, wa.x);  ffma2(acc[1], xv, wa.y);
        ffma2(acc[2], xv, wb.x);  ffma2(acc[3], xv, wb.y);
        ffma2(acc[4], xv, wc.x);  ffma2(acc[5], xv, wc.y);
        ffma2(acc[6], xv, wd.x);  ffma2(acc[7], xv, wd.y);
    }

    const int grow = row0 + row;
    const int bb = grow / 360;
    const int i = grow - bb * 360;
    u64* gdst = isv ? g_v2 : g_u2;
    #pragma unroll
    for (int j = 0; j < 8; j += 2) {
        float l0, h0, l1, h1;
        unpack2(acc[j],     l0, h0);
        unpack2(acc[j + 1], l1, h1);
        float v0 = l0 + h0, v1 = l1 + h1;      // d = ccol+j, ccol+j+1
        const int dd = ccol + j;
        if (isv) { v0 += __ldg(&bout[dd]); v1 += __ldg(&bout[dd + 1]); }
        gdst[(bb * 32 + (dd >> 1)) * RPAD + i] = pack2(v0, v1);
    }
}

// ============================================================================
// Kernel 2 (R10-proven best, ~18.0us): 64x64 tile, 2 sends x 8 recs per thread.
// uu: one conflict-free LDS.128/k; vv: 4 broadcast LDS.128/k; w: LDS.64 bcast.
// ============================================================================
__global__ __launch_bounds__(256, 4) void k2_pair(
    const float* __restrict__ Wcat,   // [64]
    const float* __restrict__ bcat,   // [1]
    float* __restrict__ out)          // [16*360*360]
{
    __shared__ u64 Us[32][64];    // [dpair][send]
    __shared__ u64 Vs[32][64];    // [dpair][rec]
    __shared__ u64 Ww[32];        // packed Wcat pairs

    const int t = threadIdx.x;
    const int b  = blockIdx.z;
    const int s0 = blockIdx.x * 64;
    const int r0 = blockIdx.y * 64;

    {
        const int c = t & 63, k0 = t >> 6;
        const u64* gu = g_u2 + b * 32 * RPAD + s0 + c;
        const u64* gv = g_v2 + b * 32 * RPAD + r0 + c;
        #pragma unroll
        for (int k = k0; k < 32; k += 4) {
            Us[k][c] = gu[k * RPAD];
            Vs[k][c] = gv[k * RPAD];
        }
        if (t < 32) Ww[t] = ((const u64*)Wcat)[t];
    }
    __syncthreads();

    const int lane = t & 31;       // sends 2*lane, 2*lane+1 (conflict-free LDS.128)
    const int wg   = t >> 5;       // recs 8*wg .. 8*wg+7 (broadcast LDS.128)

    u64 acc[8][2];
    #pragma unroll
    for (int i = 0; i < 8; i++) { acc[i][0] = 0ull; acc[i][1] = 0ull; }

    #pragma unroll 8
    for (int k = 0; k < 32; k++) {
        const u64 w2 = Ww[k];
        ulonglong2 ua = *(const ulonglong2*)&Us[k][2 * lane];
        u64 vv[8];
        #pragma unroll
        for (int q = 0; q < 4; q++) {
            ulonglong2 va = *(const ulonglong2*)&Vs[k][8 * wg + 2 * q];
            vv[2 * q] = va.x; vv[2 * q + 1] = va.y;
        }
        #pragma unroll
        for (int i = 0; i < 8; i++) {
            relu_dot2(acc[i][0], ua.x, vv[i], w2);
            relu_dot2(acc[i][1], ua.y, vv[i], w2);
        }
    }

    // Epilogue: lo+hi + b_cat, relu, float2 stores (256B coalesced per rec row)
    const float bc = __ldg(bcat);
    const int s = s0 + 2 * lane;
    if (s < R) {
        #pragma unroll
        for (int i = 0; i < 8; i++) {
            const int rec = r0 + 8 * wg + i;
            if (rec < R) {
                float l0, h0, l1, h1;
                unpack2(acc[i][0], l0, h0);
                unpack2(acc[i][1], l1, h1);
                float2 o;
                o.x = fmaxf(l0 + h0 + bc, 0.0f);
                o.y = fmaxf(l1 + h1 + bc, 0.0f);
                *(float2*)&out[((size_t)(b * R + rec)) * R + s] = o;
            }
        }
    }
}

extern "C" void kernel_launch(void* const* d_in, const int* in_sizes, int n_in,
                              void* d_out, int out_size) {
    (void)in_sizes; (void)n_in; (void)out_size;
    const float* x    = (const float*)d_in[0];  // (16,360,64)
    const float* Wout = (const float*)d_in[1];  // (128,64)
    const float* bout = (const float*)d_in[2];  // (64)
    const float* Wcat = (const float*)d_in[3];  // (64,1)
    const float* bcat = (const float*)d_in[4];  // (1)
    float* out = (float*)d_out;                 // (16,360,360,1) fp32

    k1_uv<<<360, 256>>>(x, Wout, bout);                   // 5760 rows / 16
    k2_pair<<<dim3(6, 6, 16), 256>>>(Wcat, bcat, out);    // 6 send x 6 rec x 16 batch
}